// round 1
// baseline (speedup 1.0000x reference)
#include <cuda_runtime.h>
#include <math.h>

// Problem constants
#define BATCH 128
#define NPT   500          // points per batch
#define NROWS (BATCH*NPT)  // 64000

typedef unsigned long long ull;

// ---------------- scratch (static device globals; no allocation) ----------------
// Ping-pong buffers sized for the largest intermediate: l8 = 128000 x 512 floats.
__device__ float g_bufA[65536000];
__device__ float g_bufB[65536000];
__device__ int   g_idx1[BATCH * 500];
__device__ int   g_idx2[BATCH * 1000];
__device__ float g_w3p[256 * 264];   // w3 (256x259) zero-padded to K=264
__device__ float g_w5p[384 * 392];   // w5 (384x387) zero-padded to K=392

// ---------------- weight padding ----------------
__global__ void pack_weights(const float* __restrict__ w3, const float* __restrict__ w5) {
    int t = blockIdx.x * 256 + threadIdx.x;
    const int n3 = 256 * 264;
    if (t < n3) {
        int r = t / 264, c = t - r * 264;
        g_w3p[t] = (c < 259) ? w3[r * 259 + c] : 0.f;
    }
    int t2 = t - n3;
    if (t2 >= 0 && t2 < 384 * 392) {
        int r = t2 / 392, c = t2 - r * 392;
        g_w5p[t2] = (c < 387) ? w5[r * 387 + c] : 0.f;
    }
}

// ---------------- fused conf + concat + first linear (K=4 -> 64, relu) ----------------
// thread t: point p = t/16, output group g = t%16 (4 outputs each). Writes g_bufA (64000x64).
__global__ void point_mlp1(const float* __restrict__ x,
                           const float* __restrict__ confW, const float* __restrict__ confb,
                           const float* __restrict__ w1, const float* __restrict__ b1) {
    int t = blockIdx.x * 256 + threadIdx.x;
    if (t >= NROWS * 16) return;
    int p = t >> 4, g = t & 15;
    float x0 = x[p * 3], x1 = x[p * 3 + 1], x2 = x[p * 3 + 2];
    float s = confW[0] * x0 + confW[1] * x1 + confW[2] * x2 + confb[0];
    float conf = 1.f / (1.f + expf(-s));
    const float* wr = w1 + (g * 4) * 4;   // rows g*4..g*4+3, K=4
    float v[4];
#pragma unroll
    for (int r = 0; r < 4; r++) {
        float a = b1[g * 4 + r]
                + wr[r * 4 + 0] * conf
                + wr[r * 4 + 1] * x0
                + wr[r * 4 + 2] * x1
                + wr[r * 4 + 3] * x2;
        v[r] = fmaxf(a, 0.f);
    }
    *(float4*)&g_bufA[(size_t)p * 64 + g * 4] = make_float4(v[0], v[1], v[2], v[3]);
}

// ---------------- farthest point sampling ----------------
// One warp per (batch, run). Blocks 0..127 -> FPS1 (npoint=500), 128..255 -> FPS2 (npoint=1000).
// Distances computed with EXACT unfused fp32 ops to bitwise-match XLA's sub/mul/add/add,
// argmax with first-index tie-break (matches jnp.argmax).
__global__ void fps_kernel(const float* __restrict__ x,
                           const int* __restrict__ far1, const int* __restrict__ far2) {
    int which = blockIdx.x >> 7;
    int b = blockIdx.x & 127;
    int npoint = which ? 1000 : 500;
    int* out = (which ? g_idx2 : g_idx1) + b * npoint;
    int far = which ? far2[b] : far1[b];
    const float* xb = x + (size_t)b * NPT * 3;
    int lane = threadIdx.x;

    float px[16], py[16], pz[16], dist[16];
#pragma unroll
    for (int j = 0; j < 16; j++) {
        int p = j * 32 + lane;
        if (p < NPT) {
            px[j] = xb[p * 3]; py[j] = xb[p * 3 + 1]; pz[j] = xb[p * 3 + 2];
            dist[j] = 1e10f;
        } else {
            px[j] = 0.f; py[j] = 0.f; pz[j] = 0.f;
            dist[j] = -1.0f;   // never selected: valid dists are >= 0
        }
    }

    for (int t = 0; t < npoint; t++) {
        if (lane == 0) out[t] = far;          // emit BEFORE update (matches scan)
        if (t + 1 == npoint) break;
        float cx = __ldg(xb + far * 3);
        float cy = __ldg(xb + far * 3 + 1);
        float cz = __ldg(xb + far * 3 + 2);
        float best = -2.f; int bi = 0;
#pragma unroll
        for (int j = 0; j < 16; j++) {
            float dx = __fsub_rn(px[j], cx);
            float dy = __fsub_rn(py[j], cy);
            float dz = __fsub_rn(pz[j], cz);
            float d  = __fadd_rn(__fadd_rn(__fmul_rn(dx, dx), __fmul_rn(dy, dy)),
                                 __fmul_rn(dz, dz));
            float nd = fminf(dist[j], d);
            dist[j] = nd;
            if (nd > best) { best = nd; bi = j * 32 + lane; }  // strict > keeps smallest j
        }
        // warp argmax with min-index tie-break; dists >= 0 so float bits are order-preserving
        unsigned vb = __float_as_uint(best);
        unsigned m  = __reduce_max_sync(0xffffffffu, vb);
        unsigned cand = (vb == m) ? (unsigned)bi : 0xffffffffu;
        far = (int)__reduce_min_sync(0xffffffffu, cand);
    }
}

// ---------------- SGEMM (NT): C[m,n] = relu?( sum_k A[m,k]*W[n,k] + bias[n] ) ----------------
// 128x128 block tile, BK=8, 256 threads, 8x8 per thread, Blackwell packed fp32 (fma.rn.f32x2).
// Requires: M%128==0, N%128==0, K%8==0 (all layers satisfy this after padding).
__device__ __forceinline__ ull fdup(float v) {
    ull r; unsigned u = __float_as_uint(v);
    asm("mov.b64 %0, {%1, %1};" : "=l"(r) : "r"(u));
    return r;
}
__device__ __forceinline__ void ffma2(ull& acc, ull a, ull b) {
    asm("fma.rn.f32x2 %0, %1, %2, %0;" : "+l"(acc) : "l"(a), "l"(b));
}

__global__ void __launch_bounds__(256, 2) sgemm_nt(
    const float* __restrict__ A, const float* __restrict__ W,
    const float* __restrict__ bias, float* __restrict__ C,
    int M, int N, int K, int relu)
{
    __shared__ float As[2][8][128];
    __shared__ float Bs[2][8][128];
    int tid = threadIdx.x;
    int tx = tid & 15;        // 16 col groups of 8
    int ty = tid >> 4;        // 16 row groups of 8
    int row0 = blockIdx.y << 7;
    int col0 = blockIdx.x << 7;

    int ldr = tid >> 1;           // 0..127
    int ldk = (tid & 1) << 2;     // 0 or 4
    const float* Ag = A + (size_t)(row0 + ldr) * K + ldk;
    const float* Wg = W + (size_t)(col0 + ldr) * K + ldk;

    ull acc[4][8];
#pragma unroll
    for (int i = 0; i < 4; i++)
#pragma unroll
        for (int j = 0; j < 8; j++) acc[i][j] = 0ull;

    float4 av = *(const float4*)Ag;
    float4 wv = *(const float4*)Wg;
    As[0][ldk + 0][ldr] = av.x; As[0][ldk + 1][ldr] = av.y;
    As[0][ldk + 2][ldr] = av.z; As[0][ldk + 3][ldr] = av.w;
    Bs[0][ldk + 0][ldr] = wv.x; Bs[0][ldk + 1][ldr] = wv.y;
    Bs[0][ldk + 2][ldr] = wv.z; Bs[0][ldk + 3][ldr] = wv.w;
    __syncthreads();

    int nk = K >> 3;
    for (int kt = 0; kt < nk; ++kt) {
        int cur = kt & 1;
        if (kt + 1 < nk) {
            av = *(const float4*)(Ag + (size_t)(kt + 1) * 8);
            wv = *(const float4*)(Wg + (size_t)(kt + 1) * 8);
        }
#pragma unroll
        for (int kk = 0; kk < 8; ++kk) {
            const ull* ap = (const ull*)&As[cur][kk][ty << 3];  // 4 row-pairs (8B aligned)
            ull a0 = ap[0], a1 = ap[1], a2 = ap[2], a3 = ap[3];
            const float* bp = &Bs[cur][kk][tx << 3];
            float4 b0 = *(const float4*)bp;
            float4 b1 = *(const float4*)(bp + 4);
            float bf[8] = {b0.x, b0.y, b0.z, b0.w, b1.x, b1.y, b1.z, b1.w};
#pragma unroll
            for (int j = 0; j < 8; j++) {
                ull bj = fdup(bf[j]);
                ffma2(acc[0][j], a0, bj);
                ffma2(acc[1][j], a1, bj);
                ffma2(acc[2][j], a2, bj);
                ffma2(acc[3][j], a3, bj);
            }
        }
        if (kt + 1 < nk) {
            int nxt = cur ^ 1;
            As[nxt][ldk + 0][ldr] = av.x; As[nxt][ldk + 1][ldr] = av.y;
            As[nxt][ldk + 2][ldr] = av.z; As[nxt][ldk + 3][ldr] = av.w;
            Bs[nxt][ldk + 0][ldr] = wv.x; Bs[nxt][ldk + 1][ldr] = wv.y;
            Bs[nxt][ldk + 2][ldr] = wv.z; Bs[nxt][ldk + 3][ldr] = wv.w;
            __syncthreads();
        }
    }

    float bias8[8];
#pragma unroll
    for (int j = 0; j < 8; j++) bias8[j] = __ldg(bias + col0 + (tx << 3) + j);

#pragma unroll
    for (int i = 0; i < 4; i++) {
#pragma unroll
        for (int rr = 0; rr < 2; ++rr) {
            int r = row0 + (ty << 3) + i * 2 + rr;
            float* crow = C + (size_t)r * N + col0 + (tx << 3);
            float vals[8];
#pragma unroll
            for (int j = 0; j < 8; j++) {
                unsigned bits = (rr == 0) ? (unsigned)(acc[i][j] & 0xffffffffull)
                                          : (unsigned)(acc[i][j] >> 32);
                float v = __uint_as_float(bits) + bias8[j];
                if (relu) v = fmaxf(v, 0.f);
                vals[j] = v;
            }
            *(float4*)crow       = make_float4(vals[0], vals[1], vals[2], vals[3]);
            *(float4*)(crow + 4) = make_float4(vals[4], vals[5], vals[6], vals[7]);
        }
    }
}

// ---------------- gathers (write zero padding for K alignment) ----------------
// nf1: 64000 x 264  = [ l3(256) | x(3) | 0-pad(5) ]   (l3 in g_bufA -> g_bufB)
__global__ void gather1_kernel(const float* __restrict__ x) {
    int t = blockIdx.x * 256 + threadIdx.x;
    if (t >= NROWS * 66) return;
    int r = t / 66, c4 = t - r * 66;
    int b = r / 500;
    int i = g_idx1[r];
    size_t src = (size_t)b * 500 + i;
    float4 v;
    if (c4 < 64)       v = *(const float4*)&g_bufA[src * 256 + (c4 << 2)];
    else if (c4 == 64) { const float* xp = x + src * 3; v = make_float4(xp[0], xp[1], xp[2], 0.f); }
    else               v = make_float4(0.f, 0.f, 0.f, 0.f);
    *(float4*)&g_bufB[(size_t)r * 264 + (c4 << 2)] = v;
}

// nf2: 128000 x 392 = [ l6(384) | x(3) | 0-pad(5) ]   (l6 in g_bufA -> g_bufB)
__global__ void gather2_kernel(const float* __restrict__ x) {
    int t = blockIdx.x * 256 + threadIdx.x;
    if (t >= 128000 * 98) return;
    int r = t / 98, c4 = t - r * 98;
    int b = r / 1000;
    int i = g_idx2[r];
    size_t src = (size_t)b * 500 + i;
    float4 v;
    if (c4 < 96)       v = *(const float4*)&g_bufA[src * 384 + (c4 << 2)];
    else if (c4 == 96) { const float* xp = x + src * 3; v = make_float4(xp[0], xp[1], xp[2], 0.f); }
    else               v = make_float4(0.f, 0.f, 0.f, 0.f);
    *(float4*)&g_bufB[(size_t)r * 392 + (c4 << 2)] = v;
}

// ---------------- max-pool over the 1000 sampled rows per batch ----------------
__global__ void maxpool_kernel(const float* __restrict__ l8, float* __restrict__ out) {
    int t = blockIdx.x * 256 + threadIdx.x;
    if (t >= BATCH * 512) return;
    int b = t >> 9, c = t & 511;
    const float* p = l8 + (size_t)b * 1000 * 512 + c;
    float m = -1e30f;
#pragma unroll 4
    for (int i = 0; i < 1000; i++) m = fmaxf(m, p[(size_t)i * 512]);
    out[t] = m;
}

// ---------------- launch ----------------
extern "C" void kernel_launch(void* const* d_in, const int* in_sizes, int n_in,
                              void* d_out, int out_size) {
    const float* x     = (const float*)d_in[0];
    const float* confW = (const float*)d_in[1];
    const float* confb = (const float*)d_in[2];
    const float* w1    = (const float*)d_in[3];
    const float* b1    = (const float*)d_in[4];
    const float* w2    = (const float*)d_in[5];
    const float* b2    = (const float*)d_in[6];
    const float* pc1W  = (const float*)d_in[7];
    const float* pc1b  = (const float*)d_in[8];
    const float* w3    = (const float*)d_in[9];
    const float* b3    = (const float*)d_in[10];
    const float* w4    = (const float*)d_in[11];
    const float* b4    = (const float*)d_in[12];
    const float* pc2W  = (const float*)d_in[13];
    const float* pc2b  = (const float*)d_in[14];
    const float* w5    = (const float*)d_in[15];
    const float* b5    = (const float*)d_in[16];
    const float* w6    = (const float*)d_in[17];
    const float* b6    = (const float*)d_in[18];
    // d_in[19] = model_weights (unused scalar)
    const int* far1    = (const int*)d_in[20];
    const int* far2    = (const int*)d_in[21];
    float* out = (float*)d_out;

    float *bufA, *bufB, *w3p, *w5p;
    cudaGetSymbolAddress((void**)&bufA, g_bufA);
    cudaGetSymbolAddress((void**)&bufB, g_bufB);
    cudaGetSymbolAddress((void**)&w3p,  g_w3p);
    cudaGetSymbolAddress((void**)&w5p,  g_w5p);

    // weight padding (needed by l4/l7 GEMMs)
    pack_weights<<<(256 * 264 + 384 * 392 + 255) / 256, 256>>>(w3, w5);
    // conf + feat + l1 -> bufA (64000 x 64)
    point_mlp1<<<(NROWS * 16 + 255) / 256, 256>>>(x, confW, confb, w1, b1);
    // both FPS runs concurrently (only needs x)
    fps_kernel<<<256, 32>>>(x, far1, far2);
    // l2 = relu(l1 @ w2^T + b2)   : bufA -> bufB   (64000x256, K=64)
    sgemm_nt<<<dim3(2, 500), 256>>>(bufA, w2, b2, bufB, NROWS, 256, 64, 1);
    // l3 = l2 @ pc1^T + pc1b      : bufB -> bufA   (64000x256, K=256)
    sgemm_nt<<<dim3(2, 500), 256>>>(bufB, pc1W, pc1b, bufA, NROWS, 256, 256, 0);
    // nf1 = gather(l3, idx1) ++ gather(x, idx1)    : bufA -> bufB (64000x264)
    gather1_kernel<<<(NROWS * 66 + 255) / 256, 256>>>(x);
    // l4 = relu(nf1 @ w3^T + b3)  : bufB -> bufA   (64000x256, K=264 padded)
    sgemm_nt<<<dim3(2, 500), 256>>>(bufB, w3p, b3, bufA, NROWS, 256, 264, 1);
    // l5 = relu(l4 @ w4^T + b4)   : bufA -> bufB   (64000x384, K=256)
    sgemm_nt<<<dim3(3, 500), 256>>>(bufA, w4, b4, bufB, NROWS, 384, 256, 1);
    // l6 = l5 @ pc2^T + pc2b      : bufB -> bufA   (64000x384, K=384)
    sgemm_nt<<<dim3(3, 500), 256>>>(bufB, pc2W, pc2b, bufA, NROWS, 384, 384, 0);
    // nf2 = gather(l6, idx2) ++ gather(x, idx2)    : bufA -> bufB (128000x392)
    gather2_kernel<<<(128000 * 98 + 255) / 256, 256>>>(x);
    // l7 = relu(nf2 @ w5^T + b5)  : bufB -> bufA   (128000x384, K=392 padded)
    sgemm_nt<<<dim3(3, 1000), 256>>>(bufB, w5p, b5, bufA, 128000, 384, 392, 1);
    // l8 = relu(l7 @ w6^T + b6)   : bufA -> bufB   (128000x512, K=384)
    sgemm_nt<<<dim3(4, 1000), 256>>>(bufA, w6, b6, bufB, 128000, 512, 384, 1);
    // out = max over the 1000 rows per batch
    maxpool_kernel<<<(BATCH * 512 + 255) / 256, 256>>>(bufB, out);
}